// round 2
// baseline (speedup 1.0000x reference)
#include <cuda_runtime.h>
#include <math.h>

#define NSEQ 320
#define C 128
#define H 4
#define D 32
#define NN (NSEQ*NSEQ)        // 102400
#define LN_EPS 1e-5f

// ---- scratch (device globals; no allocation) ----
__device__ float g_x[NN*C];      // layernormed act
__device__ float g_q[NN*C];      // [b][q][h*D+d], pre-scaled
__device__ float g_k[NN*C];
__device__ float g_v[NN*C];
__device__ float g_gate[NN*C];   // sigmoid applied
__device__ float g_bias[H*NN];   // TRANSPOSED: [h][k][q]
__device__ float g_wa[NN*C];     // attention out * gate

// ============================================================
// Kernel 1: LayerNorm over channels. One warp per row.
// ============================================================
__global__ void ln_kernel(const float* __restrict__ act,
                          const float* __restrict__ gamma,
                          const float* __restrict__ beta) {
    int warp = (blockIdx.x * blockDim.x + threadIdx.x) >> 5;
    int lane = threadIdx.x & 31;
    if (warp >= NN) return;
    const float4* a = (const float4*)(act + (size_t)warp * C);
    float4 v = a[lane];
    float s  = v.x + v.y + v.z + v.w;
    float s2 = v.x*v.x + v.y*v.y + v.z*v.z + v.w*v.w;
    #pragma unroll
    for (int o = 16; o > 0; o >>= 1) {
        s  += __shfl_xor_sync(0xffffffffu, s,  o);
        s2 += __shfl_xor_sync(0xffffffffu, s2, o);
    }
    float mu  = s * (1.0f / C);
    float var = s2 * (1.0f / C) - mu * mu;
    float r = rsqrtf(var + LN_EPS);
    float4 g = ((const float4*)gamma)[lane];
    float4 b = ((const float4*)beta)[lane];
    float4 o;
    o.x = (v.x - mu) * r * g.x + b.x;
    o.y = (v.y - mu) * r * g.y + b.y;
    o.z = (v.z - mu) * r * g.z + b.z;
    o.w = (v.w - mu) * r * g.w + b.w;
    ((float4*)(g_x + (size_t)warp * C))[lane] = o;
}

// ============================================================
// Kernel 2: fused projection GEMM  x[NN,128] @ B[128,516]
// cols: [0,128)=q*scale [128,256)=k [256,384)=v [384,512)=gate(sigmoid) [512,516)=pair bias
// ============================================================
__device__ __forceinline__ float fetchB(int c, int col,
    const float* __restrict__ wq, const float* __restrict__ wk,
    const float* __restrict__ wv, const float* __restrict__ wg,
    const float* __restrict__ wpb) {
    if (col < 128)      return wq[c*128 + col];
    else if (col < 256) return wk[c*128 + (col-128)];
    else if (col < 384) return wv[c*128 + (col-256)];
    else if (col < 512) return wg[c*128 + (col-384)];
    else if (col < 516) return wpb[c*4 + (col-512)];
    return 0.0f;
}

#define BM 64
#define BN 64
#define BK 16

__global__ void proj_kernel(const float* __restrict__ wq, const float* __restrict__ wk,
                            const float* __restrict__ wv, const float* __restrict__ wg,
                            const float* __restrict__ wpb) {
    __shared__ float As[BK][BM + 1];
    __shared__ float Bs[BK][BN];
    int bm = blockIdx.y * BM;
    int bn = blockIdx.x * BN;
    int tid = threadIdx.x;           // 256
    int tx = tid & 15, ty = tid >> 4;
    float acc[4][4];
    #pragma unroll
    for (int i = 0; i < 4; i++)
        #pragma unroll
        for (int j = 0; j < 4; j++) acc[i][j] = 0.0f;

    for (int k0 = 0; k0 < C; k0 += BK) {
        {   // load A tile 64x16
            int r  = tid >> 2;
            int cc = (tid & 3) * 4;
            float4 a4 = *(const float4*)(g_x + (size_t)(bm + r) * C + k0 + cc);
            As[cc+0][r] = a4.x; As[cc+1][r] = a4.y;
            As[cc+2][r] = a4.z; As[cc+3][r] = a4.w;
        }
        {   // load B tile 16x64 (on-the-fly column gather)
            int kk = tid >> 4;
            int c0 = (tid & 15) * 4;
            #pragma unroll
            for (int j = 0; j < 4; j++)
                Bs[kk][c0 + j] = fetchB(k0 + kk, bn + c0 + j, wq, wk, wv, wg, wpb);
        }
        __syncthreads();
        #pragma unroll
        for (int kk = 0; kk < BK; kk++) {
            float a[4], b[4];
            #pragma unroll
            for (int i = 0; i < 4; i++) a[i] = As[kk][ty*4 + i];
            #pragma unroll
            for (int j = 0; j < 4; j++) b[j] = Bs[kk][tx*4 + j];
            #pragma unroll
            for (int i = 0; i < 4; i++)
                #pragma unroll
                for (int j = 0; j < 4; j++) acc[i][j] += a[i] * b[j];
        }
        __syncthreads();
    }

    const float qscale = rsqrtf((float)D);
    #pragma unroll
    for (int i = 0; i < 4; i++) {
        int m = bm + ty*4 + i;
        #pragma unroll
        for (int j = 0; j < 4; j++) {
            int col = bn + tx*4 + j;
            if (col >= 516) continue;
            float val = acc[i][j];
            if (col < 128)      g_q[(size_t)m*C + col] = val * qscale;
            else if (col < 256) g_k[(size_t)m*C + (col-128)] = val;
            else if (col < 384) g_v[(size_t)m*C + (col-256)] = val;
            else if (col < 512) g_gate[(size_t)m*C + (col-384)] = 1.0f / (1.0f + __expf(-val));
            else {
                int h = col - 512;
                int qi = m / NSEQ, kj = m - qi * NSEQ;   // x row = (q,k)
                g_bias[h*NN + kj*NSEQ + qi] = val;       // store [h][k][q]
            }
        }
    }
}

// ============================================================
// Kernel 3: attention. One block per (b,h), one thread per q row.
// Online softmax over k in 2 chunks of 160 staged in smem.
// ============================================================
#define KCH 160

__global__ void attn_kernel(const int* __restrict__ pair_mask) {
    int b = blockIdx.x;
    int h = blockIdx.y;
    int q = threadIdx.x;   // 0..319
    __shared__ float Ks[KCH][D];
    __shared__ float Vs[KCH][D];
    __shared__ float msk[KCH];   // 0 = keep, nonzero = masked

    float qv[D];
    const float* qp = g_q + ((size_t)b*NSEQ + q) * C + h*D;
    #pragma unroll
    for (int dd = 0; dd < D/4; dd++) {
        float4 t = ((const float4*)qp)[dd];
        qv[4*dd+0]=t.x; qv[4*dd+1]=t.y; qv[4*dd+2]=t.z; qv[4*dd+3]=t.w;
    }
    float accv[D];
    #pragma unroll
    for (int d = 0; d < D; d++) accv[d] = 0.0f;
    float mrun = -3.0e38f, lrun = 0.0f;
    const float* biasrow = g_bias + (size_t)h * NN;   // [k][q]

    for (int kc = 0; kc < NSEQ; kc += KCH) {
        __syncthreads();
        for (int t = threadIdx.x; t < KCH * (D/4); t += blockDim.x) {
            int kk = t / (D/4);
            int dd = t - kk * (D/4);
            size_t base = ((size_t)b*NSEQ + kc + kk) * C + h*D + dd*4;
            ((float4*)Ks[kk])[dd] = *(const float4*)(g_k + base);
            ((float4*)Vs[kk])[dd] = *(const float4*)(g_v + base);
        }
        if (threadIdx.x < KCH)
            msk[threadIdx.x] = (pair_mask[(size_t)(kc + threadIdx.x)*NSEQ + b] > 0) ? 0.0f : 1.0f;
        __syncthreads();

        #pragma unroll 4
        for (int kk = 0; kk < KCH; kk++) {
            float s = 0.0f;
            #pragma unroll
            for (int dd = 0; dd < D/4; dd++) {
                float4 kf = ((const float4*)Ks[kk])[dd];
                s += qv[4*dd+0]*kf.x + qv[4*dd+1]*kf.y
                   + qv[4*dd+2]*kf.z + qv[4*dd+3]*kf.w;
            }
            s += biasrow[(size_t)(kc + kk)*NSEQ + q];
            if (msk[kk] != 0.0f) s = -1.0e9f;
            float mnew = fmaxf(mrun, s);
            float corr = __expf(mrun - mnew);
            float p    = __expf(s - mnew);
            lrun = lrun * corr + p;
            mrun = mnew;
            #pragma unroll
            for (int dd = 0; dd < D/4; dd++) {
                float4 vf = ((const float4*)Vs[kk])[dd];
                accv[4*dd+0] = accv[4*dd+0]*corr + p*vf.x;
                accv[4*dd+1] = accv[4*dd+1]*corr + p*vf.y;
                accv[4*dd+2] = accv[4*dd+2]*corr + p*vf.z;
                accv[4*dd+3] = accv[4*dd+3]*corr + p*vf.w;
            }
        }
    }

    float inv = 1.0f / lrun;
    size_t obase = ((size_t)b*NSEQ + q) * C + h*D;
    float* wp = g_wa + obase;
    const float* gp = g_gate + obase;
    #pragma unroll
    for (int dd = 0; dd < D/4; dd++) {
        float4 g4 = ((const float4*)gp)[dd];
        float4 o;
        o.x = accv[4*dd+0]*inv*g4.x;
        o.y = accv[4*dd+1]*inv*g4.y;
        o.z = accv[4*dd+2]*inv*g4.z;
        o.w = accv[4*dd+3]*inv*g4.w;
        ((float4*)wp)[dd] = o;
    }
}

// ============================================================
// Kernel 4: output GEMM  (wa*gate)[NN,128] @ w_out^T[128,128]
// ============================================================
__global__ void out_kernel(const float* __restrict__ wout, float* __restrict__ out) {
    __shared__ float As[BK][BM + 1];
    __shared__ float Bs[BK][BN];
    int bm = blockIdx.y * BM;
    int bn = blockIdx.x * BN;
    int tid = threadIdx.x;
    int tx = tid & 15, ty = tid >> 4;
    float acc[4][4];
    #pragma unroll
    for (int i = 0; i < 4; i++)
        #pragma unroll
        for (int j = 0; j < 4; j++) acc[i][j] = 0.0f;

    for (int k0 = 0; k0 < C; k0 += BK) {
        {
            int r  = tid >> 2;
            int cc = (tid & 3) * 4;
            float4 a4 = *(const float4*)(g_wa + (size_t)(bm + r) * C + k0 + cc);
            As[cc+0][r] = a4.x; As[cc+1][r] = a4.y;
            As[cc+2][r] = a4.z; As[cc+3][r] = a4.w;
        }
        {
            int kk = tid >> 4;
            int c0 = (tid & 15) * 4;
            #pragma unroll
            for (int j = 0; j < 4; j++)
                Bs[kk][c0 + j] = wout[(size_t)(bn + c0 + j)*128 + k0 + kk];  // B[c][o]=w_out[o][c]
        }
        __syncthreads();
        #pragma unroll
        for (int kk = 0; kk < BK; kk++) {
            float a[4], b[4];
            #pragma unroll
            for (int i = 0; i < 4; i++) a[i] = As[kk][ty*4 + i];
            #pragma unroll
            for (int j = 0; j < 4; j++) b[j] = Bs[kk][tx*4 + j];
            #pragma unroll
            for (int i = 0; i < 4; i++)
                #pragma unroll
                for (int j = 0; j < 4; j++) acc[i][j] += a[i] * b[j];
        }
        __syncthreads();
    }
    #pragma unroll
    for (int i = 0; i < 4; i++) {
        int m = bm + ty*4 + i;
        #pragma unroll
        for (int j = 0; j < 4; j++) {
            int col = bn + tx*4 + j;
            out[(size_t)m*C + col] = acc[i][j];
        }
    }
}

// ============================================================
extern "C" void kernel_launch(void* const* d_in, const int* in_sizes, int n_in,
                              void* d_out, int out_size) {
    const float* act   = (const float*)d_in[0];
    const int*   pmask = (const int*)  d_in[1];
    const float* gamma = (const float*)d_in[2];
    const float* beta  = (const float*)d_in[3];
    const float* wpb   = (const float*)d_in[4];
    const float* wq    = (const float*)d_in[5];
    const float* wk    = (const float*)d_in[6];
    const float* wv    = (const float*)d_in[7];
    const float* wg    = (const float*)d_in[8];
    const float* wout  = (const float*)d_in[9];
    float* out = (float*)d_out;

    ln_kernel<<<NN/8, 256>>>(act, gamma, beta);
    proj_kernel<<<dim3((516 + BN - 1)/BN, NN/BM), 256>>>(wq, wk, wv, wg, wpb);
    attn_kernel<<<dim3(NSEQ, H), NSEQ>>>(pmask);
    out_kernel<<<dim3(C/BN, NN/BM), 256>>>(wout, out);
}

// round 3
// speedup vs baseline: 1.3242x; 1.3242x over previous
#include <cuda_runtime.h>
#include <math.h>

#define NSEQ 320
#define C 128
#define H 4
#define D 32
#define NN (NSEQ*NSEQ)        // 102400
#define LN_EPS 1e-5f

// ---- scratch (device globals; no allocation) ----
__device__ float g_x[NN*C];      // layernormed act
__device__ float g_q[NN*C];      // pre-scaled
__device__ float g_k[NN*C];
__device__ float g_v[NN*C];
__device__ float g_gate[NN*C];   // sigmoid applied
__device__ float g_bias[H*NN];   // TRANSPOSED: [h][k][q]
__device__ float g_wa[NN*C];     // attention out * gate

// ---------- packed f32x2 helpers (SASS FFMA2) ----------
typedef unsigned long long u64;
__device__ __forceinline__ u64 pack2(float x, float y) {
    u64 r; asm("mov.b64 %0, {%1, %2};" : "=l"(r) : "f"(x), "f"(y)); return r;
}
__device__ __forceinline__ void unpack2(u64 v, float& x, float& y) {
    asm("mov.b64 {%0, %1}, %2;" : "=f"(x), "=f"(y) : "l"(v));
}
__device__ __forceinline__ u64 ffma2(u64 a, u64 b, u64 c) {
    u64 d; asm("fma.rn.f32x2 %0, %1, %2, %3;" : "=l"(d) : "l"(a), "l"(b), "l"(c));
    return d;
}

// ============================================================
// Kernel 1: LayerNorm + fused pair-bias projection (C->H).
// One warp per row.
// ============================================================
__global__ void ln_bias_kernel(const float* __restrict__ act,
                               const float* __restrict__ gamma,
                               const float* __restrict__ beta,
                               const float* __restrict__ wpb) {
    int warp = (blockIdx.x * blockDim.x + threadIdx.x) >> 5;
    int lane = threadIdx.x & 31;
    if (warp >= NN) return;
    const float4* a = (const float4*)(act + (size_t)warp * C);
    float4 v = a[lane];
    float s  = v.x + v.y + v.z + v.w;
    float s2 = v.x*v.x + v.y*v.y + v.z*v.z + v.w*v.w;
    #pragma unroll
    for (int o = 16; o > 0; o >>= 1) {
        s  += __shfl_xor_sync(0xffffffffu, s,  o);
        s2 += __shfl_xor_sync(0xffffffffu, s2, o);
    }
    float mu  = s * (1.0f / C);
    float var = s2 * (1.0f / C) - mu * mu;
    float r = rsqrtf(var + LN_EPS);
    float4 g = ((const float4*)gamma)[lane];
    float4 b = ((const float4*)beta)[lane];
    float4 o;
    o.x = (v.x - mu) * r * g.x + b.x;
    o.y = (v.y - mu) * r * g.y + b.y;
    o.z = (v.z - mu) * r * g.z + b.z;
    o.w = (v.w - mu) * r * g.w + b.w;
    ((float4*)(g_x + (size_t)warp * C))[lane] = o;

    // pair-bias: bias[h] = sum_c x[c] * wpb[c][h]; lane covers c=4*lane..4*lane+3
    const float4* wb = (const float4*)(wpb + lane * 16);
    float4 w0 = wb[0], w1 = wb[1], w2 = wb[2], w3 = wb[3];
    float bh[4];
    bh[0] = o.x*w0.x + o.y*w1.x + o.z*w2.x + o.w*w3.x;
    bh[1] = o.x*w0.y + o.y*w1.y + o.z*w2.y + o.w*w3.y;
    bh[2] = o.x*w0.z + o.y*w1.z + o.z*w2.z + o.w*w3.z;
    bh[3] = o.x*w0.w + o.y*w1.w + o.z*w2.w + o.w*w3.w;
    #pragma unroll
    for (int h = 0; h < 4; h++) {
        #pragma unroll
        for (int off = 16; off > 0; off >>= 1)
            bh[h] += __shfl_xor_sync(0xffffffffu, bh[h], off);
    }
    if (lane == 0) {
        int qi = warp / NSEQ;
        int kj = warp - qi * NSEQ;
        #pragma unroll
        for (int h = 0; h < 4; h++)
            g_bias[h*NN + kj*NSEQ + qi] = bh[h];   // store [h][k][q]
    }
}

// ============================================================
// Kernel 2: projection GEMM. blockIdx.x = {q,k,v,gate}, 128x128 tile,
// 8x8 microtile via FFMA2.
// ============================================================
#define PBM 128
#define PBN 128
#define PBK 16

__global__ void __launch_bounds__(256, 2)
proj_kernel(const float* __restrict__ wq, const float* __restrict__ wk,
            const float* __restrict__ wv, const float* __restrict__ wg) {
    __shared__ __align__(16) float As[PBK][PBM];
    __shared__ __align__(16) float Bs[PBK][PBN];
    int op = blockIdx.x;
    const float* W = (op == 0) ? wq : (op == 1) ? wk : (op == 2) ? wv : wg;
    float* dst = (op == 0) ? g_q : (op == 1) ? g_k : (op == 2) ? g_v : g_gate;
    int bm = blockIdx.y * PBM;
    int tid = threadIdx.x;
    int ty = tid >> 4, tx = tid & 15;

    u64 acc[8][4];
    #pragma unroll
    for (int i = 0; i < 8; i++)
        #pragma unroll
        for (int j = 0; j < 4; j++) acc[i][j] = 0ULL;

    int ar = tid >> 1, ac = (tid & 1) * 8;   // A loader: row, col-base
    int br = tid >> 4, bc = (tid & 15) * 8;  // B loader: k-row, col-base

    for (int k0 = 0; k0 < C; k0 += PBK) {
        float4 a0 = *(const float4*)(g_x + (size_t)(bm + ar) * C + k0 + ac);
        float4 a1 = *(const float4*)(g_x + (size_t)(bm + ar) * C + k0 + ac + 4);
        float4 b0 = *(const float4*)(W + (size_t)(k0 + br) * C + bc);
        float4 b1 = *(const float4*)(W + (size_t)(k0 + br) * C + bc + 4);
        __syncthreads();
        As[ac+0][ar] = a0.x; As[ac+1][ar] = a0.y; As[ac+2][ar] = a0.z; As[ac+3][ar] = a0.w;
        As[ac+4][ar] = a1.x; As[ac+5][ar] = a1.y; As[ac+6][ar] = a1.z; As[ac+7][ar] = a1.w;
        *(float4*)&Bs[br][bc]     = b0;
        *(float4*)&Bs[br][bc + 4] = b1;
        __syncthreads();
        #pragma unroll
        for (int kk = 0; kk < PBK; kk++) {
            float4 av0 = *(const float4*)&As[kk][ty*8];
            float4 av1 = *(const float4*)&As[kk][ty*8 + 4];
            ulonglong2 bv0 = *(const ulonglong2*)&Bs[kk][tx*8];
            ulonglong2 bv1 = *(const ulonglong2*)&Bs[kk][tx*8 + 4];
            u64 bb[4] = { bv0.x, bv0.y, bv1.x, bv1.y };
            float am[8] = { av0.x, av0.y, av0.z, av0.w, av1.x, av1.y, av1.z, av1.w };
            #pragma unroll
            for (int i = 0; i < 8; i++) {
                u64 a2 = pack2(am[i], am[i]);
                #pragma unroll
                for (int j = 0; j < 4; j++)
                    acc[i][j] = ffma2(a2, bb[j], acc[i][j]);
            }
        }
    }

    const float qscale = 0.17677669529663687f;  // 1/sqrt(32)
    #pragma unroll
    for (int i = 0; i < 8; i++) {
        int m = bm + ty*8 + i;
        float o[8];
        #pragma unroll
        for (int j = 0; j < 4; j++) unpack2(acc[i][j], o[2*j], o[2*j+1]);
        if (op == 0) {
            #pragma unroll
            for (int j = 0; j < 8; j++) o[j] *= qscale;
        } else if (op == 3) {
            #pragma unroll
            for (int j = 0; j < 8; j++) o[j] = 1.0f / (1.0f + __expf(-o[j]));
        }
        float4* wp = (float4*)(dst + (size_t)m * C + tx*8);
        wp[0] = make_float4(o[0], o[1], o[2], o[3]);
        wp[1] = make_float4(o[4], o[5], o[6], o[7]);
    }
}

// ============================================================
// Kernel 3: attention. Block (b,h), thread = q. No max-tracking
// (|logits| ~ O(1), masked -> p=0 exactly). FFMA2 dot + acc.
// ============================================================
#define KCH 160

__global__ void __launch_bounds__(NSEQ, 2)
attn_kernel(const int* __restrict__ pair_mask) {
    int b = blockIdx.x;
    int h = blockIdx.y;
    int q = threadIdx.x;
    __shared__ __align__(16) float Ks[KCH][D];
    __shared__ __align__(16) float Vs[KCH][D];
    __shared__ float msk[KCH];

    u64 qv2[16], acc2[16];
    {
        const float4* qp = (const float4*)(g_q + ((size_t)b*NSEQ + q) * C + h*D);
        #pragma unroll
        for (int dd = 0; dd < 8; dd++) {
            float4 t = qp[dd];
            qv2[2*dd]   = pack2(t.x, t.y);
            qv2[2*dd+1] = pack2(t.z, t.w);
        }
    }
    #pragma unroll
    for (int i = 0; i < 16; i++) acc2[i] = 0ULL;
    float lrun = 0.0f;
    const float* biasrow = g_bias + (size_t)h * NN + q;   // [k][q]

    for (int kc = 0; kc < NSEQ; kc += KCH) {
        __syncthreads();
        for (int t = threadIdx.x; t < KCH * (D/4); t += NSEQ) {
            int kk = t >> 3;
            int dd = t & 7;
            size_t base = ((size_t)b*NSEQ + kc + kk) * C + h*D + dd*4;
            ((float4*)Ks[kk])[dd] = *(const float4*)(g_k + base);
            ((float4*)Vs[kk])[dd] = *(const float4*)(g_v + base);
        }
        if (threadIdx.x < KCH)
            msk[threadIdx.x] = (pair_mask[(size_t)(kc + threadIdx.x)*NSEQ + b] > 0) ? 1.0f : 0.0f;
        __syncthreads();

        float bcur = biasrow[(size_t)kc * NSEQ];
        #pragma unroll 2
        for (int kk = 0; kk < KCH; kk++) {
            // prefetch next bias
            float bnxt = (kk + 1 < KCH) ? biasrow[(size_t)(kc + kk + 1) * NSEQ]
                                        : 0.0f;
            const ulonglong2* kp = (const ulonglong2*)Ks[kk];
            u64 d2a = 0ULL, d2b = 0ULL;
            #pragma unroll
            for (int i = 0; i < 8; i++) {
                ulonglong2 kv = kp[i];
                d2a = ffma2(qv2[2*i],   kv.x, d2a);
                d2b = ffma2(qv2[2*i+1], kv.y, d2b);
            }
            float ax, ay, bx, by;
            unpack2(d2a, ax, ay); unpack2(d2b, bx, by);
            float s = (ax + ay) + (bx + by) + bcur;
            float p = (msk[kk] != 0.0f) ? __expf(s) : 0.0f;
            lrun += p;
            u64 p2 = pack2(p, p);
            const ulonglong2* vp = (const ulonglong2*)Vs[kk];
            #pragma unroll
            for (int i = 0; i < 8; i++) {
                ulonglong2 vv = vp[i];
                acc2[2*i]   = ffma2(p2, vv.x, acc2[2*i]);
                acc2[2*i+1] = ffma2(p2, vv.y, acc2[2*i+1]);
            }
            bcur = bnxt;
        }
    }

    float inv = 1.0f / lrun;
    size_t obase = ((size_t)b*NSEQ + q) * C + h*D;
    const float4* gp = (const float4*)(g_gate + obase);
    float4* wp = (float4*)(g_wa + obase);
    #pragma unroll
    for (int dd = 0; dd < 8; dd++) {
        float4 g4 = gp[dd];
        float x0, x1, x2, x3;
        unpack2(acc2[2*dd],   x0, x1);
        unpack2(acc2[2*dd+1], x2, x3);
        wp[dd] = make_float4(x0*inv*g4.x, x1*inv*g4.y, x2*inv*g4.z, x3*inv*g4.w);
    }
}

// ============================================================
// Kernel 4: output GEMM  (wa*gate)[NN,128] @ w_out^T, FFMA2 microtile.
// ============================================================
__global__ void __launch_bounds__(256, 2)
out_kernel(const float* __restrict__ wout, float* __restrict__ out) {
    __shared__ __align__(16) float As[PBK][PBM];
    __shared__ __align__(16) float Bs[PBK][PBN];
    int bm = blockIdx.x * PBM;
    int tid = threadIdx.x;
    int ty = tid >> 4, tx = tid & 15;

    u64 acc[8][4];
    #pragma unroll
    for (int i = 0; i < 8; i++)
        #pragma unroll
        for (int j = 0; j < 4; j++) acc[i][j] = 0ULL;

    int ar = tid >> 1, ac = (tid & 1) * 8;
    int nr = tid >> 1, nc = (tid & 1) * 8;   // B loader: out-col row of wout

    for (int k0 = 0; k0 < C; k0 += PBK) {
        float4 a0 = *(const float4*)(g_wa + (size_t)(bm + ar) * C + k0 + ac);
        float4 a1 = *(const float4*)(g_wa + (size_t)(bm + ar) * C + k0 + ac + 4);
        float4 b0 = *(const float4*)(wout + (size_t)nr * C + k0 + nc);
        float4 b1 = *(const float4*)(wout + (size_t)nr * C + k0 + nc + 4);
        __syncthreads();
        As[ac+0][ar] = a0.x; As[ac+1][ar] = a0.y; As[ac+2][ar] = a0.z; As[ac+3][ar] = a0.w;
        As[ac+4][ar] = a1.x; As[ac+5][ar] = a1.y; As[ac+6][ar] = a1.z; As[ac+7][ar] = a1.w;
        Bs[nc+0][nr] = b0.x; Bs[nc+1][nr] = b0.y; Bs[nc+2][nr] = b0.z; Bs[nc+3][nr] = b0.w;
        Bs[nc+4][nr] = b1.x; Bs[nc+5][nr] = b1.y; Bs[nc+6][nr] = b1.z; Bs[nc+7][nr] = b1.w;
        __syncthreads();
        #pragma unroll
        for (int kk = 0; kk < PBK; kk++) {
            float4 av0 = *(const float4*)&As[kk][ty*8];
            float4 av1 = *(const float4*)&As[kk][ty*8 + 4];
            ulonglong2 bv0 = *(const ulonglong2*)&Bs[kk][tx*8];
            ulonglong2 bv1 = *(const ulonglong2*)&Bs[kk][tx*8 + 4];
            u64 bb[4] = { bv0.x, bv0.y, bv1.x, bv1.y };
            float am[8] = { av0.x, av0.y, av0.z, av0.w, av1.x, av1.y, av1.z, av1.w };
            #pragma unroll
            for (int i = 0; i < 8; i++) {
                u64 a2 = pack2(am[i], am[i]);
                #pragma unroll
                for (int j = 0; j < 4; j++)
                    acc[i][j] = ffma2(a2, bb[j], acc[i][j]);
            }
        }
    }

    #pragma unroll
    for (int i = 0; i < 8; i++) {
        int m = bm + ty*8 + i;
        float o[8];
        #pragma unroll
        for (int j = 0; j < 4; j++) unpack2(acc[i][j], o[2*j], o[2*j+1]);
        float4* wp = (float4*)(out + (size_t)m * C + tx*8);
        wp[0] = make_float4(o[0], o[1], o[2], o[3]);
        wp[1] = make_float4(o[4], o[5], o[6], o[7]);
    }
}

// ============================================================
extern "C" void kernel_launch(void* const* d_in, const int* in_sizes, int n_in,
                              void* d_out, int out_size) {
    const float* act   = (const float*)d_in[0];
    const int*   pmask = (const int*)  d_in[1];
    const float* gamma = (const float*)d_in[2];
    const float* beta  = (const float*)d_in[3];
    const float* wpb   = (const float*)d_in[4];
    const float* wq    = (const float*)d_in[5];
    const float* wk    = (const float*)d_in[6];
    const float* wv    = (const float*)d_in[7];
    const float* wg    = (const float*)d_in[8];
    const float* wout  = (const float*)d_in[9];
    float* out = (float*)d_out;

    ln_bias_kernel<<<NN/8, 256>>>(act, gamma, beta, wpb);
    proj_kernel<<<dim3(4, NN/PBM), 256>>>(wq, wk, wv, wg);
    attn_kernel<<<dim3(NSEQ, H), NSEQ>>>(pmask);
    out_kernel<<<NN/PBM, 256>>>(wout, out);
}

// round 5
// speedup vs baseline: 2.0496x; 1.5478x over previous
#include <cuda_runtime.h>
#include <math.h>

#define NSEQ 320
#define C 128
#define H 4
#define D 32
#define NN (NSEQ*NSEQ)        // 102400
#define LN_EPS 1e-5f

// ---- scratch (device globals; no allocation) ----
__device__ float g_x[NN*C];      // layernormed act
__device__ float g_q[NN*C];      // pre-scaled
__device__ float g_k[NN*C];
__device__ float g_v[NN*C];
__device__ float g_gate[NN*C];   // sigmoid applied
__device__ float g_bias[H*NN];   // TRANSPOSED: [h][k][q]
__device__ float g_wa[NN*C];     // attention out * gate
__device__ int   g_idx[NN];      // [b][j] compacted valid-k indices
__device__ int   g_cnt[NSEQ];    // valid count per b

// ---------- packed f32x2 helpers (SASS FFMA2) ----------
typedef unsigned long long u64;
__device__ __forceinline__ u64 pack2(float x, float y) {
    u64 r; asm("mov.b64 %0, {%1, %2};" : "=l"(r) : "f"(x), "f"(y)); return r;
}
__device__ __forceinline__ void unpack2(u64 v, float& x, float& y) {
    asm("mov.b64 {%0, %1}, %2;" : "=f"(x), "=f"(y) : "l"(v));
}
__device__ __forceinline__ u64 ffma2(u64 a, u64 b, u64 c) {
    u64 d; asm("fma.rn.f32x2 %0, %1, %2, %3;" : "=l"(d) : "l"(a), "l"(b), "l"(c));
    return d;
}

// ============================================================
// Kernel 0: per-b deterministic compaction of valid k columns.
// mask[b][k] = pair_mask[k][b] > 0. Warp-ballot prefix sum.
// ============================================================
__global__ void compact_kernel(const int* __restrict__ pm) {
    int b = blockIdx.x;
    int t = threadIdx.x;                     // 0..319
    __shared__ int wcnt[10], woff[10];
    int valid = (pm[(size_t)t * NSEQ + b] > 0) ? 1 : 0;
    unsigned ball = __ballot_sync(0xffffffffu, valid);
    int warp = t >> 5, lane = t & 31;
    if (lane == 0) wcnt[warp] = __popc(ball);
    __syncthreads();
    if (t == 0) {
        int s = 0;
        #pragma unroll
        for (int w = 0; w < 10; w++) { woff[w] = s; s += wcnt[w]; }
        g_cnt[b] = s;
    }
    __syncthreads();
    if (valid) {
        int pos = woff[warp] + __popc(ball & ((1u << lane) - 1u));
        g_idx[b * NSEQ + pos] = t;
    }
}

// ============================================================
// Kernel 1: LayerNorm + fused pair-bias projection (C->H).
// One warp per row.
// ============================================================
__global__ void ln_bias_kernel(const float* __restrict__ act,
                               const float* __restrict__ gamma,
                               const float* __restrict__ beta,
                               const float* __restrict__ wpb) {
    int warp = (blockIdx.x * blockDim.x + threadIdx.x) >> 5;
    int lane = threadIdx.x & 31;
    if (warp >= NN) return;
    const float4* a = (const float4*)(act + (size_t)warp * C);
    float4 v = a[lane];
    float s  = v.x + v.y + v.z + v.w;
    float s2 = v.x*v.x + v.y*v.y + v.z*v.z + v.w*v.w;
    #pragma unroll
    for (int o = 16; o > 0; o >>= 1) {
        s  += __shfl_xor_sync(0xffffffffu, s,  o);
        s2 += __shfl_xor_sync(0xffffffffu, s2, o);
    }
    float mu  = s * (1.0f / C);
    float var = s2 * (1.0f / C) - mu * mu;
    float r = rsqrtf(var + LN_EPS);
    float4 g = ((const float4*)gamma)[lane];
    float4 b = ((const float4*)beta)[lane];
    float4 o;
    o.x = (v.x - mu) * r * g.x + b.x;
    o.y = (v.y - mu) * r * g.y + b.y;
    o.z = (v.z - mu) * r * g.z + b.z;
    o.w = (v.w - mu) * r * g.w + b.w;
    ((float4*)(g_x + (size_t)warp * C))[lane] = o;

    // pair-bias: bias[h] = sum_c x[c] * wpb[c][h]; lane covers c=4*lane..4*lane+3
    const float4* wb = (const float4*)(wpb + lane * 16);
    float4 w0 = wb[0], w1 = wb[1], w2 = wb[2], w3 = wb[3];
    float bh[4];
    bh[0] = o.x*w0.x + o.y*w1.x + o.z*w2.x + o.w*w3.x;
    bh[1] = o.x*w0.y + o.y*w1.y + o.z*w2.y + o.w*w3.y;
    bh[2] = o.x*w0.z + o.y*w1.z + o.z*w2.z + o.w*w3.z;
    bh[3] = o.x*w0.w + o.y*w1.w + o.z*w2.w + o.w*w3.w;
    #pragma unroll
    for (int h = 0; h < 4; h++) {
        #pragma unroll
        for (int off = 16; off > 0; off >>= 1)
            bh[h] += __shfl_xor_sync(0xffffffffu, bh[h], off);
    }
    if (lane == 0) {
        int qi = warp / NSEQ;
        int kj = warp - qi * NSEQ;
        #pragma unroll
        for (int h = 0; h < 4; h++)
            g_bias[h*NN + kj*NSEQ + qi] = bh[h];   // store [h][k][q]
    }
}

// ============================================================
// Kernel 2: projection GEMM. blockIdx.x = {q,k,v,gate}, 128x128 tile,
// 8x8 microtile via FFMA2.
// ============================================================
#define PBM 128
#define PBN 128
#define PBK 16

__global__ void __launch_bounds__(256, 2)
proj_kernel(const float* __restrict__ wq, const float* __restrict__ wk,
            const float* __restrict__ wv, const float* __restrict__ wg) {
    __shared__ __align__(16) float As[PBK][PBM];
    __shared__ __align__(16) float Bs[PBK][PBN];
    int op = blockIdx.x;
    const float* W = (op == 0) ? wq : (op == 1) ? wk : (op == 2) ? wv : wg;
    float* dst = (op == 0) ? g_q : (op == 1) ? g_k : (op == 2) ? g_v : g_gate;
    int bm = blockIdx.y * PBM;
    int tid = threadIdx.x;
    int ty = tid >> 4, tx = tid & 15;

    u64 acc[8][4];
    #pragma unroll
    for (int i = 0; i < 8; i++)
        #pragma unroll
        for (int j = 0; j < 4; j++) acc[i][j] = 0ULL;

    int ar = tid >> 1, ac = (tid & 1) * 8;   // A loader: row, col-base
    int br = tid >> 4, bc = (tid & 15) * 8;  // B loader: k-row, col-base

    for (int k0 = 0; k0 < C; k0 += PBK) {
        float4 a0 = *(const float4*)(g_x + (size_t)(bm + ar) * C + k0 + ac);
        float4 a1 = *(const float4*)(g_x + (size_t)(bm + ar) * C + k0 + ac + 4);
        float4 b0 = *(const float4*)(W + (size_t)(k0 + br) * C + bc);
        float4 b1 = *(const float4*)(W + (size_t)(k0 + br) * C + bc + 4);
        __syncthreads();
        As[ac+0][ar] = a0.x; As[ac+1][ar] = a0.y; As[ac+2][ar] = a0.z; As[ac+3][ar] = a0.w;
        As[ac+4][ar] = a1.x; As[ac+5][ar] = a1.y; As[ac+6][ar] = a1.z; As[ac+7][ar] = a1.w;
        *(float4*)&Bs[br][bc]     = b0;
        *(float4*)&Bs[br][bc + 4] = b1;
        __syncthreads();
        #pragma unroll
        for (int kk = 0; kk < PBK; kk++) {
            float4 av0 = *(const float4*)&As[kk][ty*8];
            float4 av1 = *(const float4*)&As[kk][ty*8 + 4];
            ulonglong2 bv0 = *(const ulonglong2*)&Bs[kk][tx*8];
            ulonglong2 bv1 = *(const ulonglong2*)&Bs[kk][tx*8 + 4];
            u64 bb[4] = { bv0.x, bv0.y, bv1.x, bv1.y };
            float am[8] = { av0.x, av0.y, av0.z, av0.w, av1.x, av1.y, av1.z, av1.w };
            #pragma unroll
            for (int i = 0; i < 8; i++) {
                u64 a2 = pack2(am[i], am[i]);
                #pragma unroll
                for (int j = 0; j < 4; j++)
                    acc[i][j] = ffma2(a2, bb[j], acc[i][j]);
            }
        }
    }

    const float qscale = 0.17677669529663687f;  // 1/sqrt(32)
    #pragma unroll
    for (int i = 0; i < 8; i++) {
        int m = bm + ty*8 + i;
        float o[8];
        #pragma unroll
        for (int j = 0; j < 4; j++) unpack2(acc[i][j], o[2*j], o[2*j+1]);
        if (op == 0) {
            #pragma unroll
            for (int j = 0; j < 8; j++) o[j] *= qscale;
        } else if (op == 3) {
            #pragma unroll
            for (int j = 0; j < 8; j++) o[j] = 1.0f / (1.0f + __expf(-o[j]));
        }
        float4* wp = (float4*)(dst + (size_t)m * C + tx*8);
        wp[0] = make_float4(o[0], o[1], o[2], o[3]);
        wp[1] = make_float4(o[4], o[5], o[6], o[7]);
    }
}

// ============================================================
// Kernel 3: attention over COMPACTED valid keys only (~50% of 320).
// Block (b,h), thread = q. No max-tracking, no mask test in loop.
// ============================================================
#define KCH 160

__global__ void __launch_bounds__(NSEQ, 2)
attn_kernel() {
    int b = blockIdx.x;
    int h = blockIdx.y;
    int q = threadIdx.x;
    __shared__ __align__(16) float Ks[KCH][D];
    __shared__ __align__(16) float Vs[KCH][D];
    __shared__ int idxs[KCH];

    u64 qv2[16], acc2[16];
    {
        const float4* qp = (const float4*)(g_q + ((size_t)b*NSEQ + q) * C + h*D);
        #pragma unroll
        for (int dd = 0; dd < 8; dd++) {
            float4 t = qp[dd];
            qv2[2*dd]   = pack2(t.x, t.y);
            qv2[2*dd+1] = pack2(t.z, t.w);
        }
    }
    #pragma unroll
    for (int i = 0; i < 16; i++) acc2[i] = 0ULL;
    float lrun = 0.0f;
    int cnt = g_cnt[b];
    const float* biasrow = g_bias + (size_t)h * NN + q;   // [k][q]

    for (int jc = 0; jc < cnt; jc += KCH) {
        int lim = cnt - jc; if (lim > KCH) lim = KCH;
        __syncthreads();
        if (threadIdx.x < lim)
            idxs[threadIdx.x] = g_idx[b * NSEQ + jc + threadIdx.x];
        __syncthreads();
        for (int t = threadIdx.x; t < lim * (D/4); t += NSEQ) {
            int kk = t >> 3;
            int dd = t & 7;
            size_t base = ((size_t)b*NSEQ + idxs[kk]) * C + h*D + dd*4;
            ((float4*)Ks[kk])[dd] = *(const float4*)(g_k + base);
            ((float4*)Vs[kk])[dd] = *(const float4*)(g_v + base);
        }
        __syncthreads();

        float bcur = biasrow[(size_t)idxs[0] * NSEQ];
        #pragma unroll 2
        for (int kk = 0; kk < lim; kk++) {
            float bnxt = (kk + 1 < lim) ? biasrow[(size_t)idxs[kk+1] * NSEQ] : 0.0f;
            const ulonglong2* kp = (const ulonglong2*)Ks[kk];
            u64 d2a = 0ULL, d2b = 0ULL;
            #pragma unroll
            for (int i = 0; i < 8; i++) {
                ulonglong2 kv = kp[i];
                d2a = ffma2(qv2[2*i],   kv.x, d2a);
                d2b = ffma2(qv2[2*i+1], kv.y, d2b);
            }
            float ax, ay, bx, by;
            unpack2(d2a, ax, ay); unpack2(d2b, bx, by);
            float s = (ax + ay) + (bx + by) + bcur;
            float p = __expf(s);
            lrun += p;
            u64 p2 = pack2(p, p);
            const ulonglong2* vp = (const ulonglong2*)Vs[kk];
            #pragma unroll
            for (int i = 0; i < 8; i++) {
                ulonglong2 vv = vp[i];
                acc2[2*i]   = ffma2(p2, vv.x, acc2[2*i]);
                acc2[2*i+1] = ffma2(p2, vv.y, acc2[2*i+1]);
            }
            bcur = bnxt;
        }
    }

    float inv = (lrun > 0.0f) ? 1.0f / lrun : 0.0f;
    size_t obase = ((size_t)b*NSEQ + q) * C + h*D;
    const float4* gp = (const float4*)(g_gate + obase);
    float4* wp = (float4*)(g_wa + obase);
    #pragma unroll
    for (int dd = 0; dd < 8; dd++) {
        float4 g4 = gp[dd];
        float x0, x1, x2, x3;
        unpack2(acc2[2*dd],   x0, x1);
        unpack2(acc2[2*dd+1], x2, x3);
        wp[dd] = make_float4(x0*inv*g4.x, x1*inv*g4.y, x2*inv*g4.z, x3*inv*g4.w);
    }
}

// ============================================================
// Kernel 4: output GEMM  (wa*gate)[NN,128] @ w_out^T, FFMA2 microtile.
// ============================================================
__global__ void __launch_bounds__(256, 2)
out_kernel(const float* __restrict__ wout, float* __restrict__ out) {
    __shared__ __align__(16) float As[PBK][PBM];
    __shared__ __align__(16) float Bs[PBK][PBN];
    int bm = blockIdx.x * PBM;
    int tid = threadIdx.x;
    int ty = tid >> 4, tx = tid & 15;

    u64 acc[8][4];
    #pragma unroll
    for (int i = 0; i < 8; i++)
        #pragma unroll
        for (int j = 0; j < 4; j++) acc[i][j] = 0ULL;

    int ar = tid >> 1, ac = (tid & 1) * 8;
    int nr = tid >> 1, nc = (tid & 1) * 8;   // B loader: out-col row of wout

    for (int k0 = 0; k0 < C; k0 += PBK) {
        float4 a0 = *(const float4*)(g_wa + (size_t)(bm + ar) * C + k0 + ac);
        float4 a1 = *(const float4*)(g_wa + (size_t)(bm + ar) * C + k0 + ac + 4);
        float4 b0 = *(const float4*)(wout + (size_t)nr * C + k0 + nc);
        float4 b1 = *(const float4*)(wout + (size_t)nr * C + k0 + nc + 4);
        __syncthreads();
        As[ac+0][ar] = a0.x; As[ac+1][ar] = a0.y; As[ac+2][ar] = a0.z; As[ac+3][ar] = a0.w;
        As[ac+4][ar] = a1.x; As[ac+5][ar] = a1.y; As[ac+6][ar] = a1.z; As[ac+7][ar] = a1.w;
        Bs[nc+0][nr] = b0.x; Bs[nc+1][nr] = b0.y; Bs[nc+2][nr] = b0.z; Bs[nc+3][nr] = b0.w;
        Bs[nc+4][nr] = b1.x; Bs[nc+5][nr] = b1.y; Bs[nc+6][nr] = b1.z; Bs[nc+7][nr] = b1.w;
        __syncthreads();
        #pragma unroll
        for (int kk = 0; kk < PBK; kk++) {
            float4 av0 = *(const float4*)&As[kk][ty*8];
            float4 av1 = *(const float4*)&As[kk][ty*8 + 4];
            ulonglong2 bv0 = *(const ulonglong2*)&Bs[kk][tx*8];
            ulonglong2 bv1 = *(const ulonglong2*)&Bs[kk][tx*8 + 4];
            u64 bb[4] = { bv0.x, bv0.y, bv1.x, bv1.y };
            float am[8] = { av0.x, av0.y, av0.z, av0.w, av1.x, av1.y, av1.z, av1.w };
            #pragma unroll
            for (int i = 0; i < 8; i++) {
                u64 a2 = pack2(am[i], am[i]);
                #pragma unroll
                for (int j = 0; j < 4; j++)
                    acc[i][j] = ffma2(a2, bb[j], acc[i][j]);
            }
        }
    }

    #pragma unroll
    for (int i = 0; i < 8; i++) {
        int m = bm + ty*8 + i;
        float o[8];
        #pragma unroll
        for (int j = 0; j < 4; j++) unpack2(acc[i][j], o[2*j], o[2*j+1]);
        float4* wp = (float4*)(out + (size_t)m * C + tx*8);
        wp[0] = make_float4(o[0], o[1], o[2], o[3]);
        wp[1] = make_float4(o[4], o[5], o[6], o[7]);
    }
}

// ============================================================
extern "C" void kernel_launch(void* const* d_in, const int* in_sizes, int n_in,
                              void* d_out, int out_size) {
    const float* act   = (const float*)d_in[0];
    const int*   pmask = (const int*)  d_in[1];
    const float* gamma = (const float*)d_in[2];
    const float* beta  = (const float*)d_in[3];
    const float* wpb   = (const float*)d_in[4];
    const float* wq    = (const float*)d_in[5];
    const float* wk    = (const float*)d_in[6];
    const float* wv    = (const float*)d_in[7];
    const float* wg    = (const float*)d_in[8];
    const float* wout  = (const float*)d_in[9];
    float* out = (float*)d_out;

    compact_kernel<<<NSEQ, NSEQ>>>(pmask);
    ln_bias_kernel<<<NN/8, 256>>>(act, gamma, beta, wpb);
    proj_kernel<<<dim3(4, NN/PBM), 256>>>(wq, wk, wv, wg);
    attn_kernel<<<dim3(NSEQ, H), NSEQ>>>();
    out_kernel<<<NN/PBM, 256>>>(wout, out);
}

// round 6
// speedup vs baseline: 2.1169x; 1.0328x over previous
#include <cuda_runtime.h>
#include <math.h>

#define NSEQ 320
#define C 128
#define H 4
#define D 32
#define NN (NSEQ*NSEQ)        // 102400
#define LN_EPS 1e-5f

// ---- scratch (device globals; no allocation) ----
__device__ float g_x[NN*C];      // layernormed act
__device__ float g_q[NN*C];      // pre-scaled
__device__ float g_k[NN*C];
__device__ float g_v[NN*C];
__device__ float g_gate[NN*C];   // sigmoid applied
__device__ float g_bias[H*NN];   // TRANSPOSED: [h][k][q]
__device__ float g_wa[NN*C];     // attention out * gate
__device__ int   g_idx[NN];      // [b][j] compacted valid-k indices
__device__ int   g_cnt[NSEQ];    // valid count per b

// ---------- packed f32x2 helpers (SASS FFMA2) ----------
typedef unsigned long long u64;
__device__ __forceinline__ u64 pack2(float x, float y) {
    u64 r; asm("mov.b64 %0, {%1, %2};" : "=l"(r) : "f"(x), "f"(y)); return r;
}
__device__ __forceinline__ void unpack2(u64 v, float& x, float& y) {
    asm("mov.b64 {%0, %1}, %2;" : "=f"(x), "=f"(y) : "l"(v));
}
__device__ __forceinline__ u64 ffma2(u64 a, u64 b, u64 c) {
    u64 d; asm("fma.rn.f32x2 %0, %1, %2, %3;" : "=l"(d) : "l"(a), "l"(b), "l"(c));
    return d;
}

// ============================================================
// Kernel 0: per-b deterministic compaction of valid k columns.
// ============================================================
__global__ void compact_kernel(const int* __restrict__ pm) {
    int b = blockIdx.x;
    int t = threadIdx.x;                     // 0..319
    __shared__ int wcnt[10], woff[10];
    int valid = (pm[(size_t)t * NSEQ + b] > 0) ? 1 : 0;
    unsigned ball = __ballot_sync(0xffffffffu, valid);
    int warp = t >> 5, lane = t & 31;
    if (lane == 0) wcnt[warp] = __popc(ball);
    __syncthreads();
    if (t == 0) {
        int s = 0;
        #pragma unroll
        for (int w = 0; w < 10; w++) { woff[w] = s; s += wcnt[w]; }
        g_cnt[b] = s;
    }
    __syncthreads();
    if (valid) {
        int pos = woff[warp] + __popc(ball & ((1u << lane) - 1u));
        g_idx[b * NSEQ + pos] = t;
    }
}

// ============================================================
// Kernel 1: LayerNorm + fused pair-bias projection (C->H).
// ============================================================
__global__ void ln_bias_kernel(const float* __restrict__ act,
                               const float* __restrict__ gamma,
                               const float* __restrict__ beta,
                               const float* __restrict__ wpb) {
    int warp = (blockIdx.x * blockDim.x + threadIdx.x) >> 5;
    int lane = threadIdx.x & 31;
    if (warp >= NN) return;
    const float4* a = (const float4*)(act + (size_t)warp * C);
    float4 v = a[lane];
    float s  = v.x + v.y + v.z + v.w;
    float s2 = v.x*v.x + v.y*v.y + v.z*v.z + v.w*v.w;
    #pragma unroll
    for (int o = 16; o > 0; o >>= 1) {
        s  += __shfl_xor_sync(0xffffffffu, s,  o);
        s2 += __shfl_xor_sync(0xffffffffu, s2, o);
    }
    float mu  = s * (1.0f / C);
    float var = s2 * (1.0f / C) - mu * mu;
    float r = rsqrtf(var + LN_EPS);
    float4 g = ((const float4*)gamma)[lane];
    float4 b = ((const float4*)beta)[lane];
    float4 o;
    o.x = (v.x - mu) * r * g.x + b.x;
    o.y = (v.y - mu) * r * g.y + b.y;
    o.z = (v.z - mu) * r * g.z + b.z;
    o.w = (v.w - mu) * r * g.w + b.w;
    ((float4*)(g_x + (size_t)warp * C))[lane] = o;

    const float4* wb = (const float4*)(wpb + lane * 16);
    float4 w0 = wb[0], w1 = wb[1], w2 = wb[2], w3 = wb[3];
    float bh[4];
    bh[0] = o.x*w0.x + o.y*w1.x + o.z*w2.x + o.w*w3.x;
    bh[1] = o.x*w0.y + o.y*w1.y + o.z*w2.y + o.w*w3.y;
    bh[2] = o.x*w0.z + o.y*w1.z + o.z*w2.z + o.w*w3.z;
    bh[3] = o.x*w0.w + o.y*w1.w + o.z*w2.w + o.w*w3.w;
    #pragma unroll
    for (int h = 0; h < 4; h++) {
        #pragma unroll
        for (int off = 16; off > 0; off >>= 1)
            bh[h] += __shfl_xor_sync(0xffffffffu, bh[h], off);
    }
    if (lane == 0) {
        int qi = warp / NSEQ;
        int kj = warp - qi * NSEQ;
        #pragma unroll
        for (int h = 0; h < 4; h++)
            g_bias[h*NN + kj*NSEQ + qi] = bh[h];   // store [h][k][q]
    }
}

// ============================================================
// Kernel 2: projection GEMM. blockIdx.x = {q,k,v,gate}, 128x128 tile.
// ============================================================
#define PBM 128
#define PBN 128
#define PBK 16

__global__ void __launch_bounds__(256, 2)
proj_kernel(const float* __restrict__ wq, const float* __restrict__ wk,
            const float* __restrict__ wv, const float* __restrict__ wg) {
    __shared__ __align__(16) float As[PBK][PBM];
    __shared__ __align__(16) float Bs[PBK][PBN];
    int op = blockIdx.x;
    const float* W = (op == 0) ? wq : (op == 1) ? wk : (op == 2) ? wv : wg;
    float* dst = (op == 0) ? g_q : (op == 1) ? g_k : (op == 2) ? g_v : g_gate;
    int bm = blockIdx.y * PBM;
    int tid = threadIdx.x;
    int ty = tid >> 4, tx = tid & 15;

    u64 acc[8][4];
    #pragma unroll
    for (int i = 0; i < 8; i++)
        #pragma unroll
        for (int j = 0; j < 4; j++) acc[i][j] = 0ULL;

    int ar = tid >> 1, ac = (tid & 1) * 8;
    int br = tid >> 4, bc = (tid & 15) * 8;

    for (int k0 = 0; k0 < C; k0 += PBK) {
        float4 a0 = *(const float4*)(g_x + (size_t)(bm + ar) * C + k0 + ac);
        float4 a1 = *(const float4*)(g_x + (size_t)(bm + ar) * C + k0 + ac + 4);
        float4 b0 = *(const float4*)(W + (size_t)(k0 + br) * C + bc);
        float4 b1 = *(const float4*)(W + (size_t)(k0 + br) * C + bc + 4);
        __syncthreads();
        As[ac+0][ar] = a0.x; As[ac+1][ar] = a0.y; As[ac+2][ar] = a0.z; As[ac+3][ar] = a0.w;
        As[ac+4][ar] = a1.x; As[ac+5][ar] = a1.y; As[ac+6][ar] = a1.z; As[ac+7][ar] = a1.w;
        *(float4*)&Bs[br][bc]     = b0;
        *(float4*)&Bs[br][bc + 4] = b1;
        __syncthreads();
        #pragma unroll
        for (int kk = 0; kk < PBK; kk++) {
            float4 av0 = *(const float4*)&As[kk][ty*8];
            float4 av1 = *(const float4*)&As[kk][ty*8 + 4];
            ulonglong2 bv0 = *(const ulonglong2*)&Bs[kk][tx*8];
            ulonglong2 bv1 = *(const ulonglong2*)&Bs[kk][tx*8 + 4];
            u64 bb[4] = { bv0.x, bv0.y, bv1.x, bv1.y };
            float am[8] = { av0.x, av0.y, av0.z, av0.w, av1.x, av1.y, av1.z, av1.w };
            #pragma unroll
            for (int i = 0; i < 8; i++) {
                u64 a2 = pack2(am[i], am[i]);
                #pragma unroll
                for (int j = 0; j < 4; j++)
                    acc[i][j] = ffma2(a2, bb[j], acc[i][j]);
            }
        }
    }

    const float qscale = 0.17677669529663687f;  // 1/sqrt(32)
    #pragma unroll
    for (int i = 0; i < 8; i++) {
        int m = bm + ty*8 + i;
        float o[8];
        #pragma unroll
        for (int j = 0; j < 4; j++) unpack2(acc[i][j], o[2*j], o[2*j+1]);
        if (op == 0) {
            #pragma unroll
            for (int j = 0; j < 8; j++) o[j] *= qscale;
        } else if (op == 3) {
            #pragma unroll
            for (int j = 0; j < 8; j++) o[j] = 1.0f / (1.0f + __expf(-o[j]));
        }
        float4* wp = (float4*)(dst + (size_t)m * C + tx*8);
        wp[0] = make_float4(o[0], o[1], o[2], o[3]);
        wp[1] = make_float4(o[4], o[5], o[6], o[7]);
    }
}

// ============================================================
// Kernel 3: attention, compacted keys, 2 q-rows per thread.
// Block (b,h), 160 threads; thread covers q = tid and tid+160.
// K/V shared loads amortized over both q accumulators.
// ============================================================
#define KCH 160
#define QB 160

__global__ void __launch_bounds__(QB, 2)
attn_kernel() {
    int b = blockIdx.x;
    int h = blockIdx.y;
    int q0 = threadIdx.x;
    int q1 = threadIdx.x + QB;
    __shared__ __align__(16) float Ks[KCH][D];
    __shared__ __align__(16) float Vs[KCH][D];
    __shared__ int idxs[KCH];

    u64 qva[16], qvb[16], acca[16], accb[16];
    {
        const float4* qp = (const float4*)(g_q + ((size_t)b*NSEQ + q0) * C + h*D);
        const float4* rp = (const float4*)(g_q + ((size_t)b*NSEQ + q1) * C + h*D);
        #pragma unroll
        for (int dd = 0; dd < 8; dd++) {
            float4 t = qp[dd];
            qva[2*dd]   = pack2(t.x, t.y);
            qva[2*dd+1] = pack2(t.z, t.w);
            float4 u = rp[dd];
            qvb[2*dd]   = pack2(u.x, u.y);
            qvb[2*dd+1] = pack2(u.z, u.w);
        }
    }
    #pragma unroll
    for (int i = 0; i < 16; i++) { acca[i] = 0ULL; accb[i] = 0ULL; }
    float la = 0.0f, lb = 0.0f;
    int cnt = g_cnt[b];
    const float* biasrow = g_bias + (size_t)h * NN;   // [k][q]

    for (int jc = 0; jc < cnt; jc += KCH) {
        int lim = cnt - jc; if (lim > KCH) lim = KCH;
        __syncthreads();
        if (threadIdx.x < lim)
            idxs[threadIdx.x] = g_idx[b * NSEQ + jc + threadIdx.x];
        __syncthreads();
        for (int t = threadIdx.x; t < lim * (D/4); t += QB) {
            int kk = t >> 3;
            int dd = t & 7;
            size_t base = ((size_t)b*NSEQ + idxs[kk]) * C + h*D + dd*4;
            ((float4*)Ks[kk])[dd] = *(const float4*)(g_k + base);
            ((float4*)Vs[kk])[dd] = *(const float4*)(g_v + base);
        }
        __syncthreads();

        int icur = idxs[0];
        float bca = biasrow[(size_t)icur * NSEQ + q0];
        float bcb = biasrow[(size_t)icur * NSEQ + q1];
        #pragma unroll 1
        for (int kk = 0; kk < lim; kk++) {
            float bna = 0.0f, bnb = 0.0f;
            if (kk + 1 < lim) {
                int inxt = idxs[kk+1];
                bna = biasrow[(size_t)inxt * NSEQ + q0];
                bnb = biasrow[(size_t)inxt * NSEQ + q1];
            }
            const ulonglong2* kp = (const ulonglong2*)Ks[kk];
            u64 da0 = 0ULL, da1 = 0ULL, db0 = 0ULL, db1 = 0ULL;
            #pragma unroll
            for (int i = 0; i < 8; i++) {
                ulonglong2 kv = kp[i];
                da0 = ffma2(qva[2*i],   kv.x, da0);
                da1 = ffma2(qva[2*i+1], kv.y, da1);
                db0 = ffma2(qvb[2*i],   kv.x, db0);
                db1 = ffma2(qvb[2*i+1], kv.y, db1);
            }
            float ax, ay, az, aw, bx, by, bz, bw;
            unpack2(da0, ax, ay); unpack2(da1, az, aw);
            unpack2(db0, bx, by); unpack2(db1, bz, bw);
            float sa = (ax + ay) + (az + aw) + bca;
            float sb = (bx + by) + (bz + bw) + bcb;
            float pa = __expf(sa);
            float pb = __expf(sb);
            la += pa; lb += pb;
            u64 pa2 = pack2(pa, pa);
            u64 pb2 = pack2(pb, pb);
            const ulonglong2* vp = (const ulonglong2*)Vs[kk];
            #pragma unroll
            for (int i = 0; i < 8; i++) {
                ulonglong2 vv = vp[i];
                acca[2*i]   = ffma2(pa2, vv.x, acca[2*i]);
                acca[2*i+1] = ffma2(pa2, vv.y, acca[2*i+1]);
                accb[2*i]   = ffma2(pb2, vv.x, accb[2*i]);
                accb[2*i+1] = ffma2(pb2, vv.y, accb[2*i+1]);
            }
            bca = bna; bcb = bnb;
        }
    }

    float iva = (la > 0.0f) ? 1.0f / la : 0.0f;
    float ivb = (lb > 0.0f) ? 1.0f / lb : 0.0f;
    {
        size_t obase = ((size_t)b*NSEQ + q0) * C + h*D;
        const float4* gp = (const float4*)(g_gate + obase);
        float4* wp = (float4*)(g_wa + obase);
        #pragma unroll
        for (int dd = 0; dd < 8; dd++) {
            float4 g4 = gp[dd];
            float x0, x1, x2, x3;
            unpack2(acca[2*dd],   x0, x1);
            unpack2(acca[2*dd+1], x2, x3);
            wp[dd] = make_float4(x0*iva*g4.x, x1*iva*g4.y, x2*iva*g4.z, x3*iva*g4.w);
        }
    }
    {
        size_t obase = ((size_t)b*NSEQ + q1) * C + h*D;
        const float4* gp = (const float4*)(g_gate + obase);
        float4* wp = (float4*)(g_wa + obase);
        #pragma unroll
        for (int dd = 0; dd < 8; dd++) {
            float4 g4 = gp[dd];
            float x0, x1, x2, x3;
            unpack2(accb[2*dd],   x0, x1);
            unpack2(accb[2*dd+1], x2, x3);
            wp[dd] = make_float4(x0*ivb*g4.x, x1*ivb*g4.y, x2*ivb*g4.z, x3*ivb*g4.w);
        }
    }
}

// ============================================================
// Kernel 4: output GEMM  (wa*gate)[NN,128] @ w_out^T, FFMA2 microtile.
// ============================================================
__global__ void __launch_bounds__(256, 2)
out_kernel(const float* __restrict__ wout, float* __restrict__ out) {
    __shared__ __align__(16) float As[PBK][PBM];
    __shared__ __align__(16) float Bs[PBK][PBN];
    int bm = blockIdx.x * PBM;
    int tid = threadIdx.x;
    int ty = tid >> 4, tx = tid & 15;

    u64 acc[8][4];
    #pragma unroll
    for (int i = 0; i < 8; i++)
        #pragma unroll
        for (int j = 0; j < 4; j++) acc[i][j] = 0ULL;

    int ar = tid >> 1, ac = (tid & 1) * 8;
    int nr = tid >> 1, nc = (tid & 1) * 8;

    for (int k0 = 0; k0 < C; k0 += PBK) {
        float4 a0 = *(const float4*)(g_wa + (size_t)(bm + ar) * C + k0 + ac);
        float4 a1 = *(const float4*)(g_wa + (size_t)(bm + ar) * C + k0 + ac + 4);
        float4 b0 = *(const float4*)(wout + (size_t)nr * C + k0 + nc);
        float4 b1 = *(const float4*)(wout + (size_t)nr * C + k0 + nc + 4);
        __syncthreads();
        As[ac+0][ar] = a0.x; As[ac+1][ar] = a0.y; As[ac+2][ar] = a0.z; As[ac+3][ar] = a0.w;
        As[ac+4][ar] = a1.x; As[ac+5][ar] = a1.y; As[ac+6][ar] = a1.z; As[ac+7][ar] = a1.w;
        Bs[nc+0][nr] = b0.x; Bs[nc+1][nr] = b0.y; Bs[nc+2][nr] = b0.z; Bs[nc+3][nr] = b0.w;
        Bs[nc+4][nr] = b1.x; Bs[nc+5][nr] = b1.y; Bs[nc+6][nr] = b1.z; Bs[nc+7][nr] = b1.w;
        __syncthreads();
        #pragma unroll
        for (int kk = 0; kk < PBK; kk++) {
            float4 av0 = *(const float4*)&As[kk][ty*8];
            float4 av1 = *(const float4*)&As[kk][ty*8 + 4];
            ulonglong2 bv0 = *(const ulonglong2*)&Bs[kk][tx*8];
            ulonglong2 bv1 = *(const ulonglong2*)&Bs[kk][tx*8 + 4];
            u64 bb[4] = { bv0.x, bv0.y, bv1.x, bv1.y };
            float am[8] = { av0.x, av0.y, av0.z, av0.w, av1.x, av1.y, av1.z, av1.w };
            #pragma unroll
            for (int i = 0; i < 8; i++) {
                u64 a2 = pack2(am[i], am[i]);
                #pragma unroll
                for (int j = 0; j < 4; j++)
                    acc[i][j] = ffma2(a2, bb[j], acc[i][j]);
            }
        }
    }

    #pragma unroll
    for (int i = 0; i < 8; i++) {
        int m = bm + ty*8 + i;
        float o[8];
        #pragma unroll
        for (int j = 0; j < 4; j++) unpack2(acc[i][j], o[2*j], o[2*j+1]);
        float4* wp = (float4*)(out + (size_t)m * C + tx*8);
        wp[0] = make_float4(o[0], o[1], o[2], o[3]);
        wp[1] = make_float4(o[4], o[5], o[6], o[7]);
    }
}

// ============================================================
extern "C" void kernel_launch(void* const* d_in, const int* in_sizes, int n_in,
                              void* d_out, int out_size) {
    const float* act   = (const float*)d_in[0];
    const int*   pmask = (const int*)  d_in[1];
    const float* gamma = (const float*)d_in[2];
    const float* beta  = (const float*)d_in[3];
    const float* wpb   = (const float*)d_in[4];
    const float* wq    = (const float*)d_in[5];
    const float* wk    = (const float*)d_in[6];
    const float* wv    = (const float*)d_in[7];
    const float* wg    = (const float*)d_in[8];
    const float* wout  = (const float*)d_in[9];
    float* out = (float*)d_out;

    compact_kernel<<<NSEQ, NSEQ>>>(pmask);
    ln_bias_kernel<<<NN/8, 256>>>(act, gamma, beta, wpb);
    proj_kernel<<<dim3(4, NN/PBM), 256>>>(wq, wk, wv, wg);
    attn_kernel<<<dim3(NSEQ, H), QB>>>();
    out_kernel<<<NN/PBM, 256>>>(wout, out);
}

// round 8
// speedup vs baseline: 2.4205x; 1.1434x over previous
#include <cuda_runtime.h>
#include <math.h>
#include <stdint.h>

#define NSEQ 320
#define C 128
#define H 4
#define D 32
#define NN (NSEQ*NSEQ)        // 102400
#define LN_EPS 1e-5f

// ---- scratch (device globals; no allocation) ----
__device__ float g_x[NN*C];      // layernormed act
__device__ float g_q[NN*C];      // pre-scaled
__device__ float g_k[NN*C];
__device__ float g_v[NN*C];
__device__ float g_gate[NN*C];   // sigmoid applied
__device__ float g_bias[H*NN];   // TRANSPOSED: [h][k][q]
__device__ float g_wa[NN*C];     // attention out * gate
__device__ int   g_idx[NN];      // [b][j] compacted valid-k indices
__device__ int   g_cnt[NSEQ];    // valid count per b

// ---------- packed f32x2 helpers (SASS FFMA2) ----------
typedef unsigned long long u64;
__device__ __forceinline__ u64 pack2(float x, float y) {
    u64 r; asm("mov.b64 %0, {%1, %2};" : "=l"(r) : "f"(x), "f"(y)); return r;
}
__device__ __forceinline__ void unpack2(u64 v, float& x, float& y) {
    asm("mov.b64 {%0, %1}, %2;" : "=f"(x), "=f"(y) : "l"(v));
}
__device__ __forceinline__ u64 ffma2(u64 a, u64 b, u64 c) {
    u64 d; asm("fma.rn.f32x2 %0, %1, %2, %3;" : "=l"(d) : "l"(a), "l"(b), "l"(c));
    return d;
}

// ---------- tf32 mma helpers (base sm_103, no 'a' feature needed) ----------
__device__ __forceinline__ uint32_t tf32b(float x) {
    uint32_t u; asm("cvt.rna.tf32.f32 %0, %1;" : "=r"(u) : "f"(x)); return u;
}
__device__ __forceinline__ void split_tf32(float x, uint32_t& hi, uint32_t& lo) {
    hi = tf32b(x);
    lo = tf32b(x - __uint_as_float(hi));
}
__device__ __forceinline__ void mma8(float* d_, const uint32_t* a, const uint32_t* b) {
    asm volatile(
        "mma.sync.aligned.m16n8k8.row.col.f32.tf32.tf32.f32 "
        "{%0,%1,%2,%3}, {%4,%5,%6,%7}, {%8,%9}, {%0,%1,%2,%3};"
        : "+f"(d_[0]), "+f"(d_[1]), "+f"(d_[2]), "+f"(d_[3])
        : "r"(a[0]), "r"(a[1]), "r"(a[2]), "r"(a[3]), "r"(b[0]), "r"(b[1]));
}

// ============================================================
// Kernel 0: per-b deterministic compaction of valid k columns.
// ============================================================
__global__ void compact_kernel(const int* __restrict__ pm) {
    int b = blockIdx.x;
    int t = threadIdx.x;                     // 0..319
    __shared__ int wcnt[10], woff[10];
    int valid = (pm[(size_t)t * NSEQ + b] > 0) ? 1 : 0;
    unsigned ball = __ballot_sync(0xffffffffu, valid);
    int warp = t >> 5, lane = t & 31;
    if (lane == 0) wcnt[warp] = __popc(ball);
    __syncthreads();
    if (t == 0) {
        int s = 0;
        #pragma unroll
        for (int w = 0; w < 10; w++) { woff[w] = s; s += wcnt[w]; }
        g_cnt[b] = s;
    }
    __syncthreads();
    if (valid) {
        int pos = woff[warp] + __popc(ball & ((1u << lane) - 1u));
        g_idx[b * NSEQ + pos] = t;
    }
}

// ============================================================
// Kernel 1: LayerNorm + fused pair-bias projection (C->H).
// ============================================================
__global__ void ln_bias_kernel(const float* __restrict__ act,
                               const float* __restrict__ gamma,
                               const float* __restrict__ beta,
                               const float* __restrict__ wpb) {
    int warp = (blockIdx.x * blockDim.x + threadIdx.x) >> 5;
    int lane = threadIdx.x & 31;
    if (warp >= NN) return;
    const float4* a = (const float4*)(act + (size_t)warp * C);
    float4 v = a[lane];
    float s  = v.x + v.y + v.z + v.w;
    float s2 = v.x*v.x + v.y*v.y + v.z*v.z + v.w*v.w;
    #pragma unroll
    for (int o = 16; o > 0; o >>= 1) {
        s  += __shfl_xor_sync(0xffffffffu, s,  o);
        s2 += __shfl_xor_sync(0xffffffffu, s2, o);
    }
    float mu  = s * (1.0f / C);
    float var = s2 * (1.0f / C) - mu * mu;
    float r = rsqrtf(var + LN_EPS);
    float4 g = ((const float4*)gamma)[lane];
    float4 b = ((const float4*)beta)[lane];
    float4 o;
    o.x = (v.x - mu) * r * g.x + b.x;
    o.y = (v.y - mu) * r * g.y + b.y;
    o.z = (v.z - mu) * r * g.z + b.z;
    o.w = (v.w - mu) * r * g.w + b.w;
    ((float4*)(g_x + (size_t)warp * C))[lane] = o;

    const float4* wb = (const float4*)(wpb + lane * 16);
    float4 w0 = wb[0], w1 = wb[1], w2 = wb[2], w3 = wb[3];
    float bh[4];
    bh[0] = o.x*w0.x + o.y*w1.x + o.z*w2.x + o.w*w3.x;
    bh[1] = o.x*w0.y + o.y*w1.y + o.z*w2.y + o.w*w3.y;
    bh[2] = o.x*w0.z + o.y*w1.z + o.z*w2.z + o.w*w3.z;
    bh[3] = o.x*w0.w + o.y*w1.w + o.z*w2.w + o.w*w3.w;
    #pragma unroll
    for (int h = 0; h < 4; h++) {
        #pragma unroll
        for (int off = 16; off > 0; off >>= 1)
            bh[h] += __shfl_xor_sync(0xffffffffu, bh[h], off);
    }
    if (lane == 0) {
        int qi = warp / NSEQ;
        int kj = warp - qi * NSEQ;
        #pragma unroll
        for (int h = 0; h < 4; h++)
            g_bias[h*NN + kj*NSEQ + qi] = bh[h];   // store [h][k][q]
    }
}

// ============================================================
// Kernel 2: projection GEMMs via mma.sync tf32 (3xTF32 split).
// grid (4 ops, 800 m-tiles); block 256 = 8 warps (2m x 4n).
// A[m][k] stride 36; B[k][n] stride 132. Warp tile 64x32.
// ============================================================
__global__ void __launch_bounds__(256)
proj_mma(const float* __restrict__ wq, const float* __restrict__ wk,
         const float* __restrict__ wv, const float* __restrict__ wg) {
    __shared__ __align__(16) float As[128*36];
    __shared__ __align__(16) float Bs[32*132];
    int op = blockIdx.x;
    const float* W = (op == 0) ? wq : (op == 1) ? wk : (op == 2) ? wv : wg;
    float* dst = (op == 0) ? g_q : (op == 1) ? g_k : (op == 2) ? g_v : g_gate;
    int bm = blockIdx.y * 128;
    int tid = threadIdx.x;
    int wid = tid >> 5, lane = tid & 31;
    int wm = (wid >> 2) * 64, wn = (wid & 3) * 32;
    int lr = lane >> 2, lc = lane & 3;

    float acc[4][4][4];
    #pragma unroll
    for (int mi = 0; mi < 4; mi++)
        #pragma unroll
        for (int ni = 0; ni < 4; ni++)
            #pragma unroll
            for (int e = 0; e < 4; e++) acc[mi][ni][e] = 0.0f;

    for (int k0 = 0; k0 < C; k0 += 32) {
        #pragma unroll
        for (int i = 0; i < 4; i++) {
            int e = i * 256 + tid;
            int r = e >> 3, c = (e & 7) * 4;
            float4 v = *(const float4*)(g_x + (size_t)(bm + r) * C + k0 + c);
            As[r*36 + c] = v.x; As[r*36 + c + 1] = v.y;
            As[r*36 + c + 2] = v.z; As[r*36 + c + 3] = v.w;
        }
        #pragma unroll
        for (int i = 0; i < 4; i++) {
            int e = i * 256 + tid;
            int r = e >> 5, c = (e & 31) * 4;
            *(float4*)&Bs[r*132 + c] = *(const float4*)(W + (size_t)(k0 + r) * C + c);
        }
        __syncthreads();
        #pragma unroll
        for (int kc = 0; kc < 4; kc++) {
            int kb = kc * 8 + lc;
            uint32_t ahi[4][4], alo[4][4];
            #pragma unroll
            for (int mi = 0; mi < 4; mi++) {
                int r0 = wm + mi * 16 + lr;
                split_tf32(As[r0*36 + kb],       ahi[mi][0], alo[mi][0]);
                split_tf32(As[(r0+8)*36 + kb],   ahi[mi][1], alo[mi][1]);
                split_tf32(As[r0*36 + kb + 4],   ahi[mi][2], alo[mi][2]);
                split_tf32(As[(r0+8)*36 + kb+4], ahi[mi][3], alo[mi][3]);
            }
            uint32_t bhi[4][2], blo[4][2];
            #pragma unroll
            for (int ni = 0; ni < 4; ni++) {
                int n0 = wn + ni * 8 + lr;
                split_tf32(Bs[kb*132 + n0],       bhi[ni][0], blo[ni][0]);
                split_tf32(Bs[(kb+4)*132 + n0],   bhi[ni][1], blo[ni][1]);
            }
            #pragma unroll
            for (int mi = 0; mi < 4; mi++)
                #pragma unroll
                for (int ni = 0; ni < 4; ni++) {
                    mma8(acc[mi][ni], ahi[mi], bhi[ni]);
                    mma8(acc[mi][ni], ahi[mi], blo[ni]);
                    mma8(acc[mi][ni], alo[mi], bhi[ni]);
                }
        }
        __syncthreads();
    }

    const float qscale = 0.17677669529663687f;   // 1/sqrt(32)
    #pragma unroll
    for (int mi = 0; mi < 4; mi++) {
        #pragma unroll
        for (int ni = 0; ni < 4; ni++) {
            int row = bm + wm + mi * 16 + lr;
            int col = wn + ni * 8 + 2 * lc;
            float v0 = acc[mi][ni][0], v1 = acc[mi][ni][1];
            float v2 = acc[mi][ni][2], v3 = acc[mi][ni][3];
            if (op == 0) { v0 *= qscale; v1 *= qscale; v2 *= qscale; v3 *= qscale; }
            else if (op == 3) {
                v0 = 1.0f/(1.0f+__expf(-v0)); v1 = 1.0f/(1.0f+__expf(-v1));
                v2 = 1.0f/(1.0f+__expf(-v2)); v3 = 1.0f/(1.0f+__expf(-v3));
            }
            *(float2*)(dst + (size_t)row * C + col)     = make_float2(v0, v1);
            *(float2*)(dst + (size_t)(row+8) * C + col) = make_float2(v2, v3);
        }
    }
}

// ============================================================
// Kernel 4: output GEMM (wa)[NN,128] @ w_out^T via mma.sync tf32.
// B tile stored [n][k] stride 36 (wout rows are already K-major).
// ============================================================
__global__ void __launch_bounds__(256)
out_mma(const float* __restrict__ wout, float* __restrict__ out) {
    __shared__ __align__(16) float As[128*36];
    __shared__ __align__(16) float Bs[128*36];
    int bm = blockIdx.x * 128;
    int tid = threadIdx.x;
    int wid = tid >> 5, lane = tid & 31;
    int wm = (wid >> 2) * 64, wn = (wid & 3) * 32;
    int lr = lane >> 2, lc = lane & 3;

    float acc[4][4][4];
    #pragma unroll
    for (int mi = 0; mi < 4; mi++)
        #pragma unroll
        for (int ni = 0; ni < 4; ni++)
            #pragma unroll
            for (int e = 0; e < 4; e++) acc[mi][ni][e] = 0.0f;

    for (int k0 = 0; k0 < C; k0 += 32) {
        #pragma unroll
        for (int i = 0; i < 4; i++) {
            int e = i * 256 + tid;
            int r = e >> 3, c = (e & 7) * 4;
            float4 v = *(const float4*)(g_wa + (size_t)(bm + r) * C + k0 + c);
            As[r*36 + c] = v.x; As[r*36 + c + 1] = v.y;
            As[r*36 + c + 2] = v.z; As[r*36 + c + 3] = v.w;
            float4 w4 = *(const float4*)(wout + (size_t)r * C + k0 + c);
            *(float4*)&Bs[r*36 + c] = w4;
        }
        __syncthreads();
        #pragma unroll
        for (int kc = 0; kc < 4; kc++) {
            int kb = kc * 8 + lc;
            uint32_t ahi[4][4], alo[4][4];
            #pragma unroll
            for (int mi = 0; mi < 4; mi++) {
                int r0 = wm + mi * 16 + lr;
                split_tf32(As[r0*36 + kb],       ahi[mi][0], alo[mi][0]);
                split_tf32(As[(r0+8)*36 + kb],   ahi[mi][1], alo[mi][1]);
                split_tf32(As[r0*36 + kb + 4],   ahi[mi][2], alo[mi][2]);
                split_tf32(As[(r0+8)*36 + kb+4], ahi[mi][3], alo[mi][3]);
            }
            uint32_t bhi[4][2], blo[4][2];
            #pragma unroll
            for (int ni = 0; ni < 4; ni++) {
                int n0 = wn + ni * 8 + lr;
                split_tf32(Bs[n0*36 + kb],     bhi[ni][0], blo[ni][0]);
                split_tf32(Bs[n0*36 + kb + 4], bhi[ni][1], blo[ni][1]);
            }
            #pragma unroll
            for (int mi = 0; mi < 4; mi++)
                #pragma unroll
                for (int ni = 0; ni < 4; ni++) {
                    mma8(acc[mi][ni], ahi[mi], bhi[ni]);
                    mma8(acc[mi][ni], ahi[mi], blo[ni]);
                    mma8(acc[mi][ni], alo[mi], bhi[ni]);
                }
        }
        __syncthreads();
    }

    #pragma unroll
    for (int mi = 0; mi < 4; mi++) {
        #pragma unroll
        for (int ni = 0; ni < 4; ni++) {
            int row = bm + wm + mi * 16 + lr;
            int col = wn + ni * 8 + 2 * lc;
            *(float2*)(out + (size_t)row * C + col)
                = make_float2(acc[mi][ni][0], acc[mi][ni][1]);
            *(float2*)(out + (size_t)(row+8) * C + col)
                = make_float2(acc[mi][ni][2], acc[mi][ni][3]);
        }
    }
}

// ============================================================
// Kernel 3: attention, compacted keys, 2 q-rows per thread.
// ============================================================
#define KCH 160
#define QB 160

__global__ void __launch_bounds__(QB, 2)
attn_kernel() {
    int b = blockIdx.x;
    int h = blockIdx.y;
    int q0 = threadIdx.x;
    int q1 = threadIdx.x + QB;
    __shared__ __align__(16) float Ks[KCH][D];
    __shared__ __align__(16) float Vs[KCH][D];
    __shared__ int idxs[KCH];

    u64 qva[16], qvb[16], acca[16], accb[16];
    {
        const float4* qp = (const float4*)(g_q + ((size_t)b*NSEQ + q0) * C + h*D);
        const float4* rp = (const float4*)(g_q + ((size_t)b*NSEQ + q1) * C + h*D);
        #pragma unroll
        for (int dd = 0; dd < 8; dd++) {
            float4 t = qp[dd];
            qva[2*dd]   = pack2(t.x, t.y);
            qva[2*dd+1] = pack2(t.z, t.w);
            float4 u = rp[dd];
            qvb[2*dd]   = pack2(u.x, u.y);
            qvb[2*dd+1] = pack2(u.z, u.w);
        }
    }
    #pragma unroll
    for (int i = 0; i < 16; i++) { acca[i] = 0ULL; accb[i] = 0ULL; }
    float la = 0.0f, lb = 0.0f;
    int cnt = g_cnt[b];
    const float* biasrow = g_bias + (size_t)h * NN;   // [k][q]

    for (int jc = 0; jc < cnt; jc += KCH) {
        int lim = cnt - jc; if (lim > KCH) lim = KCH;
        __syncthreads();
        if (threadIdx.x < lim)
            idxs[threadIdx.x] = g_idx[b * NSEQ + jc + threadIdx.x];
        __syncthreads();
        for (int t = threadIdx.x; t < lim * (D/4); t += QB) {
            int kk = t >> 3;
            int dd = t & 7;
            size_t base = ((size_t)b*NSEQ + idxs[kk]) * C + h*D + dd*4;
            ((float4*)Ks[kk])[dd] = *(const float4*)(g_k + base);
            ((float4*)Vs[kk])[dd] = *(const float4*)(g_v + base);
        }
        __syncthreads();

        int icur = idxs[0];
        float bca = biasrow[(size_t)icur * NSEQ + q0];
        float bcb = biasrow[(size_t)icur * NSEQ + q1];
        #pragma unroll 1
        for (int kk = 0; kk < lim; kk++) {
            float bna = 0.0f, bnb = 0.0f;
            if (kk + 1 < lim) {
                int inxt = idxs[kk+1];
                bna = biasrow[(size_t)inxt * NSEQ + q0];
                bnb = biasrow[(size_t)inxt * NSEQ + q1];
            }
            const ulonglong2* kp = (const ulonglong2*)Ks[kk];
            u64 da0 = 0ULL, da1 = 0ULL, db0 = 0ULL, db1 = 0ULL;
            #pragma unroll
            for (int i = 0; i < 8; i++) {
                ulonglong2 kv = kp[i];
                da0 = ffma2(qva[2*i],   kv.x, da0);
                da1 = ffma2(qva[2*i+1], kv.y, da1);
                db0 = ffma2(qvb[2*i],   kv.x, db0);
                db1 = ffma2(qvb[2*i+1], kv.y, db1);
            }
            float ax, ay, az, aw, bx, by, bz, bw;
            unpack2(da0, ax, ay); unpack2(da1, az, aw);
            unpack2(db0, bx, by); unpack2(db1, bz, bw);
            float sa = (ax + ay) + (az + aw) + bca;
            float sb2 = (bx + by) + (bz + bw) + bcb;
            float pa = __expf(sa);
            float pb = __expf(sb2);
            la += pa; lb += pb;
            u64 pa2 = pack2(pa, pa);
            u64 pb2 = pack2(pb, pb);
            const ulonglong2* vp = (const ulonglong2*)Vs[kk];
            #pragma unroll
            for (int i = 0; i < 8; i++) {
                ulonglong2 vv = vp[i];
                acca[2*i]   = ffma2(pa2, vv.x, acca[2*i]);
                acca[2*i+1] = ffma2(pa2, vv.y, acca[2*i+1]);
                accb[2*i]   = ffma2(pb2, vv.x, accb[2*i]);
                accb[2*i+1] = ffma2(pb2, vv.y, accb[2*i+1]);
            }
            bca = bna; bcb = bnb;
        }
    }

    float iva = (la > 0.0f) ? 1.0f / la : 0.0f;
    float ivb = (lb > 0.0f) ? 1.0f / lb : 0.0f;
    {
        size_t obase = ((size_t)b*NSEQ + q0) * C + h*D;
        const float4* gp = (const float4*)(g_gate + obase);
        float4* wp = (float4*)(g_wa + obase);
        #pragma unroll
        for (int dd = 0; dd < 8; dd++) {
            float4 g4 = gp[dd];
            float x0, x1, x2, x3;
            unpack2(acca[2*dd],   x0, x1);
            unpack2(acca[2*dd+1], x2, x3);
            wp[dd] = make_float4(x0*iva*g4.x, x1*iva*g4.y, x2*iva*g4.z, x3*iva*g4.w);
        }
    }
    {
        size_t obase = ((size_t)b*NSEQ + q1) * C + h*D;
        const float4* gp = (const float4*)(g_gate + obase);
        float4* wp = (float4*)(g_wa + obase);
        #pragma unroll
        for (int dd = 0; dd < 8; dd++) {
            float4 g4 = gp[dd];
            float x0, x1, x2, x3;
            unpack2(accb[2*dd],   x0, x1);
            unpack2(accb[2*dd+1], x2, x3);
            wp[dd] = make_float4(x0*ivb*g4.x, x1*ivb*g4.y, x2*ivb*g4.z, x3*ivb*g4.w);
        }
    }
}

// ============================================================
extern "C" void kernel_launch(void* const* d_in, const int* in_sizes, int n_in,
                              void* d_out, int out_size) {
    const float* act   = (const float*)d_in[0];
    const int*   pmask = (const int*)  d_in[1];
    const float* gamma = (const float*)d_in[2];
    const float* beta  = (const float*)d_in[3];
    const float* wpb   = (const float*)d_in[4];
    const float* wq    = (const float*)d_in[5];
    const float* wk    = (const float*)d_in[6];
    const float* wv    = (const float*)d_in[7];
    const float* wg    = (const float*)d_in[8];
    const float* wout  = (const float*)d_in[9];
    float* out = (float*)d_out;

    compact_kernel<<<NSEQ, NSEQ>>>(pmask);
    ln_bias_kernel<<<NN/8, 256>>>(act, gamma, beta, wpb);
    proj_mma<<<dim3(4, NN/128), 256>>>(wq, wk, wv, wg);
    attn_kernel<<<dim3(NSEQ, H), QB>>>();
    out_mma<<<NN/128, 256>>>(wout, out);
}